// round 7
// baseline (speedup 1.0000x reference)
#include <cuda_runtime.h>
#include <cuda_bf16.h>
#include <math.h>
#include <cstdint>

// ---------------- problem constants ----------------
#define L       2048
#define D       768
#define ED      1536
#define NL      4
#define NST     16
#define DTR     48
#define DXP     80
#define VOCAB   32000
#define DCONV   4
#define CHUNK   64
#define NCHUNK  (L / CHUNK)

// ---------------- scratch ----------------
__device__ __align__(256) float g_x    [L * D];
__device__ __align__(256) float g_xz   [L * 2 * ED];
__device__ __align__(256) float g_xb   [L * ED];
__device__ __align__(256) float g_dbc  [L * DXP];
__device__ __align__(256) float g_delta[L * ED];
__device__ __align__(256) float g_cp   [NCHUNK * ED * NST];
__device__ __align__(256) float g_cs   [NCHUNK * ED * NST];
__device__ __align__(256) float g_cc   [NCHUNK * ED * NST];
__device__ __align__(256) __nv_bfloat16 g_ah[L * ED];
__device__ __align__(256) __nv_bfloat16 g_al[L * ED];
__device__ __align__(256) __nv_bfloat16 g_dh[L * 64];
__device__ __align__(256) __nv_bfloat16 g_dl[L * 64];
__device__ __align__(256) __nv_bfloat16 g_wh[VOCAB * D];
__device__ __align__(256) __nv_bfloat16 g_wl[VOCAB * D];

// ---------------- helpers ----------------
__device__ __forceinline__ uint32_t smem_u32(const void* p) {
    uint32_t a;
    asm("{ .reg .u64 t; cvta.to.shared.u64 t, %1; cvt.u32.u64 %0, t; }" : "=r"(a) : "l"(p));
    return a;
}
__device__ __forceinline__ void ldsm4(uint32_t* r, uint32_t addr) {
    asm volatile("ldmatrix.sync.aligned.m8n8.x4.shared.b16 {%0,%1,%2,%3}, [%4];"
                 : "=r"(r[0]), "=r"(r[1]), "=r"(r[2]), "=r"(r[3]) : "r"(addr));
}
__device__ __forceinline__ void mma_bf16(float* d, const uint32_t* a, const uint32_t* b) {
    asm volatile(
        "mma.sync.aligned.m16n8k16.row.col.f32.bf16.bf16.f32 "
        "{%0,%1,%2,%3}, {%4,%5,%6,%7}, {%8,%9}, {%0,%1,%2,%3};"
        : "+f"(d[0]), "+f"(d[1]), "+f"(d[2]), "+f"(d[3])
        : "r"(a[0]), "r"(a[1]), "r"(a[2]), "r"(a[3]), "r"(b[0]), "r"(b[1]));
}
__device__ __forceinline__ void cpa16(uint32_t d, const void* s) {
    asm volatile("cp.async.cg.shared.global [%0], [%1], 16;" :: "r"(d), "l"(s));
}
#define CP_COMMIT() asm volatile("cp.async.commit_group;" ::: "memory")
#define CP_WAIT0()  asm volatile("cp.async.wait_group 0;" ::: "memory")

// ---------------- embedding ----------------
__global__ void embed_k(const int* __restrict__ tok, const float* __restrict__ emb,
                        float* __restrict__ x) {
    int i = blockIdx.x * blockDim.x + threadIdx.x;
    if (i >= L * D) return;
    int t = i / D, d = i % D;
    x[i] = emb[(size_t)tok[t] * D + d];
}

// ---------------- fp32 -> bf16 hi/lo split ----------------
__global__ void split4_k(const float4* __restrict__ src, __nv_bfloat162* __restrict__ hi,
                         __nv_bfloat162* __restrict__ lo, int n4) {
    int i = blockIdx.x * blockDim.x + threadIdx.x;
    if (i >= n4) return;
    float4 v = src[i];
    __nv_bfloat16 hx = __float2bfloat16(v.x), hy = __float2bfloat16(v.y);
    __nv_bfloat16 hz = __float2bfloat16(v.z), hw = __float2bfloat16(v.w);
    hi[2 * i]     = __nv_bfloat162(hx, hy);
    hi[2 * i + 1] = __nv_bfloat162(hz, hw);
    lo[2 * i]     = __nv_bfloat162(__float2bfloat16(v.x - __bfloat162float(hx)),
                                   __float2bfloat16(v.y - __bfloat162float(hy)));
    lo[2 * i + 1] = __nv_bfloat162(__float2bfloat16(v.z - __bfloat162float(hz)),
                                   __float2bfloat16(v.w - __bfloat162float(hw)));
}

// padded split
__global__ void split_pad_k(const float* __restrict__ src, __nv_bfloat16* __restrict__ hi,
                            __nv_bfloat16* __restrict__ lo,
                            int Mdst, int Kp, int Msrc, int Kin, int Ssrc) {
    int i = blockIdx.x * blockDim.x + threadIdx.x;
    if (i >= Mdst * Kp) return;
    int r = i / Kp, c = i % Kp;
    float v = (r < Msrc && c < Kin) ? src[(size_t)r * Ssrc + c] : 0.f;
    __nv_bfloat16 h = __float2bfloat16(v);
    hi[i] = h;
    lo[i] = __float2bfloat16(v - __bfloat162float(h));
}

// ---------------- RMSNorm -> bf16 hi/lo ----------------
__global__ void rmsnorm_split_k(const float* __restrict__ x, const float* __restrict__ w,
                                __nv_bfloat16* __restrict__ oh, __nv_bfloat16* __restrict__ ol) {
    int t = blockIdx.x;
    const float* xr = x + (size_t)t * D;
    float s = 0.f;
    for (int d = threadIdx.x; d < D; d += 256) { float v = xr[d]; s += v * v; }
    __shared__ float red[256];
    red[threadIdx.x] = s;
    __syncthreads();
    for (int o = 128; o > 0; o >>= 1) {
        if (threadIdx.x < o) red[threadIdx.x] += red[threadIdx.x + o];
        __syncthreads();
    }
    float inv = rsqrtf(red[0] / (float)D + 1e-5f);
    for (int d = threadIdx.x; d < D; d += 256) {
        float v = xr[d] * inv * w[d];
        __nv_bfloat16 h = __float2bfloat16(v);
        oh[(size_t)t * D + d] = h;
        ol[(size_t)t * D + d] = __float2bfloat16(v - __bfloat162float(h));
    }
}

// ---------------- conv1d + silu, fused bf16 hi/lo split of output ----------------
__global__ void conv_silu_split_k(const float* __restrict__ xz, const float* __restrict__ w,
                                  const float* __restrict__ b, float* __restrict__ xb,
                                  __nv_bfloat16* __restrict__ oh, __nv_bfloat16* __restrict__ ol) {
    int i = blockIdx.x * blockDim.x + threadIdx.x;
    if (i >= L * ED) return;
    int t = i / ED, e = i % ED;
    const float* wr = w + e * DCONV;
    float acc = b[e];
#pragma unroll
    for (int j = 0; j < DCONV; j++) {
        int tt = t - (DCONV - 1) + j;
        if (tt >= 0) acc = fmaf(xz[(size_t)tt * (2 * ED) + e], wr[j], acc);
    }
    float v = acc / (1.f + __expf(-acc));
    xb[i] = v;
    __nv_bfloat16 h = __float2bfloat16(v);
    oh[i] = h;
    ol[i] = __float2bfloat16(v - __bfloat162float(h));
}

// ---------------- bf16 3-term split GEMM (generic, 256 thr, (MT*32)x128 tile) ----------------
#define ROWB 80

template<int MT, int EPI>
__global__ __launch_bounds__(256, 2) void hgemm_k(
    const __nv_bfloat16* __restrict__ Ah, const __nv_bfloat16* __restrict__ Al,
    const __nv_bfloat16* __restrict__ Bh, const __nv_bfloat16* __restrict__ Bl,
    float* __restrict__ C, int K, int ldc, int Nlim, const float* __restrict__ aux)
{
    constexpr int ASZ   = MT * 32 * ROWB;
    constexpr int BSZ   = 128 * ROWB;
    constexpr int BUFSZ = 2 * ASZ + 2 * BSZ;

    extern __shared__ char dynsm[];
    uint32_t base = smem_u32(dynsm);

    int tid = threadIdx.x, lane = tid & 31, wid = tid >> 5;
    int m0 = blockIdx.x * (MT * 32), n0 = blockIdx.y * 128;
    int wm = (wid & 1) * (MT * 16), wn = (wid >> 1) * 32;

    int lr = tid >> 2;
    int lk = (tid & 3) * 8;

    const __nv_bfloat16* gAh0 = Ah + (size_t)(m0 + lr) * K + lk;
    const __nv_bfloat16* gAl0 = Al + (size_t)(m0 + lr) * K + lk;
    const __nv_bfloat16* gAh1 = (MT == 4) ? gAh0 + (size_t)64 * K : gAh0;
    const __nv_bfloat16* gAl1 = (MT == 4) ? gAl0 + (size_t)64 * K : gAl0;
    const __nv_bfloat16* gBh0 = Bh + (size_t)(n0 + lr) * K + lk;
    const __nv_bfloat16* gBl0 = Bl + (size_t)(n0 + lr) * K + lk;
    const __nv_bfloat16* gBh1 = gBh0 + (size_t)64 * K;
    const __nv_bfloat16* gBl1 = gBl0 + (size_t)64 * K;

    uint32_t st0 = (uint32_t)(lr * ROWB + lk * 2);
    uint32_t st1 = st0 + 64 * ROWB;

    uint32_t aOff = (uint32_t)((wm + (lane & 15)) * ROWB + (lane >> 4) * 16);
    uint32_t bOff4 = (uint32_t)((wn + ((lane >> 4) << 3) + (lane & 7)) * ROWB
                                + ((lane >> 3) & 1) * 16);

    float acc[MT][4][4];
#pragma unroll
    for (int i = 0; i < MT; i++)
#pragma unroll
        for (int j = 0; j < 4; j++)
#pragma unroll
            for (int r = 0; r < 4; r++) acc[i][j][r] = 0.f;

    int nchunk = K >> 5;

    auto prefetch = [&](int kc, int buf) {
        int ko = kc * 32;
        uint32_t bo = base + buf * BUFSZ;
        if (MT == 4) {
            cpa16(bo + st0, gAh0 + ko);        cpa16(bo + st1, gAh1 + ko);
            cpa16(bo + ASZ + st0, gAl0 + ko);  cpa16(bo + ASZ + st1, gAl1 + ko);
        } else if (MT == 2) {
            cpa16(bo + st0, gAh0 + ko);
            cpa16(bo + ASZ + st0, gAl0 + ko);
        } else {
            if (lr < 32) {
                cpa16(bo + st0, gAh0 + ko);
                cpa16(bo + ASZ + st0, gAl0 + ko);
            }
        }
        cpa16(bo + 2 * ASZ + st0, gBh0 + ko);        cpa16(bo + 2 * ASZ + st1, gBh1 + ko);
        cpa16(bo + 2 * ASZ + BSZ + st0, gBl0 + ko);  cpa16(bo + 2 * ASZ + BSZ + st1, gBl1 + ko);
    };

    prefetch(0, 0);
    CP_COMMIT();

    for (int kc = 0; kc < nchunk; kc++) {
        CP_WAIT0();
        __syncthreads();
        if (kc + 1 < nchunk) prefetch(kc + 1, (kc + 1) & 1);
        CP_COMMIT();

        uint32_t bo = base + (kc & 1) * BUFSZ;
#pragma unroll
        for (int kk = 0; kk < 2; kk++) {
            uint32_t kb = kk * 32;
            uint32_t bh4[2][4], bl4[2][4];
#pragma unroll
            for (int p = 0; p < 2; p++) {
                uint32_t off = bOff4 + p * 16 * ROWB + kb;
                ldsm4(bh4[p], bo + 2 * ASZ + off);
                ldsm4(bl4[p], bo + 2 * ASZ + BSZ + off);
            }
#pragma unroll
            for (int mt = 0; mt < MT; mt++) {
                uint32_t ah[4];
                ldsm4(ah, bo + aOff + mt * 16 * ROWB + kb);
#pragma unroll
                for (int nt = 0; nt < 4; nt++)
                    mma_bf16(acc[mt][nt], ah, &bh4[nt >> 1][(nt & 1) * 2]);
#pragma unroll
                for (int nt = 0; nt < 4; nt++)
                    mma_bf16(acc[mt][nt], ah, &bl4[nt >> 1][(nt & 1) * 2]);
            }
#pragma unroll
            for (int mt = 0; mt < MT; mt++) {
                uint32_t al[4];
                ldsm4(al, bo + ASZ + aOff + mt * 16 * ROWB + kb);
#pragma unroll
                for (int nt = 0; nt < 4; nt++)
                    mma_bf16(acc[mt][nt], al, &bh4[nt >> 1][(nt & 1) * 2]);
            }
        }
    }

    int er = m0 + wm + (lane >> 2);
    int ec = n0 + wn + (lane & 3) * 2;
#pragma unroll
    for (int mt = 0; mt < MT; mt++) {
#pragma unroll
        for (int nt = 0; nt < 4; nt++) {
            int col = ec + nt * 8;
            if (col >= Nlim) continue;
            float* p0 = C + (size_t)(er + mt * 16) * ldc + col;
            float* p1 = p0 + 8 * ldc;
            float d0 = acc[mt][nt][0], d1 = acc[mt][nt][1];
            float d2 = acc[mt][nt][2], d3 = acc[mt][nt][3];
            if (EPI == 1) {
                float b0 = aux[col], b1 = aux[col + 1];
                d0 += b0; d1 += b1; d2 += b0; d3 += b1;
                d0 = (d0 > 20.f) ? d0 : log1pf(__expf(d0));
                d1 = (d1 > 20.f) ? d1 : log1pf(__expf(d1));
                d2 = (d2 > 20.f) ? d2 : log1pf(__expf(d2));
                d3 = (d3 > 20.f) ? d3 : log1pf(__expf(d3));
            } else if (EPI == 2) {
                float2 o0 = *(float2*)p0, o1 = *(float2*)p1;
                d0 += o0.x; d1 += o0.y; d2 += o1.x; d3 += o1.y;
            }
            *(float2*)p0 = make_float2(d0, d1);
            *(float2*)p1 = make_float2(d2, d3);
        }
    }
}

// ---------------- big-tile GEMM: 256x256 per CTA, 512 threads ----------------
// Warp grid 4x4, warp tile 64x64. Same 3-term split. For the lm_head GEMM.
__global__ __launch_bounds__(512, 1) void hgemm2_k(
    const __nv_bfloat16* __restrict__ Ah, const __nv_bfloat16* __restrict__ Al,
    const __nv_bfloat16* __restrict__ Bh, const __nv_bfloat16* __restrict__ Bl,
    float* __restrict__ C, int K, int ldc)
{
    constexpr int TSZ   = 256 * ROWB;       // 20480 bytes per array per buffer
    constexpr int BUFSZ = 4 * TSZ;          // Ah, Al, Bh, Bl

    extern __shared__ char dynsm[];
    uint32_t base = smem_u32(dynsm);

    int tid = threadIdx.x, lane = tid & 31, wid = tid >> 5;
    int m0 = blockIdx.x * 256, n0 = blockIdx.y * 256;
    int wm = (wid & 3) * 64, wn = (wid >> 2) * 64;

    int lr = tid >> 2;             // 0..127
    int lk = (tid & 3) * 8;

    const __nv_bfloat16* gAh0 = Ah + (size_t)(m0 + lr) * K + lk;
    const __nv_bfloat16* gAl0 = Al + (size_t)(m0 + lr) * K + lk;
    const __nv_bfloat16* gBh0 = Bh + (size_t)(n0 + lr) * K + lk;
    const __nv_bfloat16* gBl0 = Bl + (size_t)(n0 + lr) * K + lk;
    const size_t rstep = (size_t)128 * K;

    uint32_t st0 = (uint32_t)(lr * ROWB + lk * 2);
    uint32_t st1 = st0 + 128 * ROWB;

    uint32_t aOff = (uint32_t)((wm + (lane & 15)) * ROWB + (lane >> 4) * 16);
    uint32_t bOff4 = (uint32_t)((wn + ((lane >> 4) << 3) + (lane & 7)) * ROWB
                                + ((lane >> 3) & 1) * 16);

    float acc[4][8][4];
#pragma unroll
    for (int i = 0; i < 4; i++)
#pragma unroll
        for (int j = 0; j < 8; j++)
#pragma unroll
            for (int r = 0; r < 4; r++) acc[i][j][r] = 0.f;

    int nchunk = K >> 5;

    auto prefetch = [&](int kc, int buf) {
        int ko = kc * 32;
        uint32_t bo = base + buf * BUFSZ;
        cpa16(bo + st0,           gAh0 + ko);  cpa16(bo + st1,           gAh0 + rstep + ko);
        cpa16(bo + TSZ + st0,     gAl0 + ko);  cpa16(bo + TSZ + st1,     gAl0 + rstep + ko);
        cpa16(bo + 2 * TSZ + st0, gBh0 + ko);  cpa16(bo + 2 * TSZ + st1, gBh0 + rstep + ko);
        cpa16(bo + 3 * TSZ + st0, gBl0 + ko);  cpa16(bo + 3 * TSZ + st1, gBl0 + rstep + ko);
    };

    prefetch(0, 0);
    CP_COMMIT();

    for (int kc = 0; kc < nchunk; kc++) {
        CP_WAIT0();
        __syncthreads();
        if (kc + 1 < nchunk) prefetch(kc + 1, (kc + 1) & 1);
        CP_COMMIT();

        uint32_t bo = base + (kc & 1) * BUFSZ;
#pragma unroll
        for (int kk = 0; kk < 2; kk++) {
            uint32_t kb = kk * 32;
            // resident fragments: Bh (4 pairs => 8 nt) and Ah (4 mt)
            uint32_t bh4[4][4];
#pragma unroll
            for (int p = 0; p < 4; p++)
                ldsm4(bh4[p], bo + 2 * TSZ + bOff4 + p * 16 * ROWB + kb);
            uint32_t ah4[4][4];
#pragma unroll
            for (int mt = 0; mt < 4; mt++)
                ldsm4(ah4[mt], bo + aOff + mt * 16 * ROWB + kb);
            // term 1: Ah * Bh
#pragma unroll
            for (int mt = 0; mt < 4; mt++)
#pragma unroll
                for (int nt = 0; nt < 8; nt++)
                    mma_bf16(acc[mt][nt], ah4[mt], &bh4[nt >> 1][(nt & 1) * 2]);
            // term 2: Al * Bh (streamed)
#pragma unroll
            for (int mt = 0; mt < 4; mt++) {
                uint32_t al[4];
                ldsm4(al, bo + TSZ + aOff + mt * 16 * ROWB + kb);
#pragma unroll
                for (int nt = 0; nt < 8; nt++)
                    mma_bf16(acc[mt][nt], al, &bh4[nt >> 1][(nt & 1) * 2]);
            }
            // term 3: Ah * Bl (streamed)
#pragma unroll
            for (int p = 0; p < 4; p++) {
                uint32_t bl[4];
                ldsm4(bl, bo + 3 * TSZ + bOff4 + p * 16 * ROWB + kb);
#pragma unroll
                for (int mt = 0; mt < 4; mt++) {
                    mma_bf16(acc[mt][2 * p],     ah4[mt], &bl[0]);
                    mma_bf16(acc[mt][2 * p + 1], ah4[mt], &bl[2]);
                }
            }
        }
    }

    int er = m0 + wm + (lane >> 2);
    int ec = n0 + wn + (lane & 3) * 2;
#pragma unroll
    for (int mt = 0; mt < 4; mt++) {
#pragma unroll
        for (int nt = 0; nt < 8; nt++) {
            float* p0 = C + (size_t)(er + mt * 16) * ldc + ec + nt * 8;
            float* p1 = p0 + 8 * ldc;
            *(float2*)p0 = make_float2(acc[mt][nt][0], acc[mt][nt][1]);
            *(float2*)p1 = make_float2(acc[mt][nt][2], acc[mt][nt][3]);
        }
    }
}

// ---------------- selective scan ----------------
__global__ void scan1_k(const float* __restrict__ delta, const float* __restrict__ xb,
                        const float* __restrict__ dbc, const float* __restrict__ A_log,
                        float* __restrict__ cp, float* __restrict__ cs) {
    int i = blockIdx.x * blockDim.x + threadIdx.x;
    if (i >= NCHUNK * ED) return;
    int c = i / ED, e = i % ED;
    float A[NST], h[NST], p[NST];
#pragma unroll
    for (int n = 0; n < NST; n++) {
        A[n] = -__expf(A_log[e * NST + n]);
        h[n] = 0.f; p[n] = 1.f;
    }
    int t0 = c * CHUNK;
    for (int t = t0; t < t0 + CHUNK; t++) {
        float d  = delta[(size_t)t * ED + e];
        float xv = xb[(size_t)t * ED + e];
        float dx = d * xv;
        const float* Bt = dbc + (size_t)t * DXP + DTR;
#pragma unroll
        for (int n = 0; n < NST; n++) {
            float a = __expf(d * A[n]);
            p[n] *= a;
            h[n] = fmaf(a, h[n], dx * Bt[n]);
        }
    }
    size_t o = (size_t)i * NST;
#pragma unroll
    for (int n = 0; n < NST; n++) { cp[o + n] = p[n]; cs[o + n] = h[n]; }
}

__global__ void carry_k(const float* __restrict__ cp, const float* __restrict__ cs,
                        float* __restrict__ cc) {
    int i = blockIdx.x * blockDim.x + threadIdx.x;
    if (i >= ED * NST) return;
    float H = 0.f;
    for (int c = 0; c < NCHUNK; c++) {
        size_t idx = (size_t)c * ED * NST + i;
        cc[idx] = H;
        H = fmaf(cp[idx], H, cs[idx]);
    }
}

__global__ void scan2_k(const float* __restrict__ delta, const float* __restrict__ xb,
                        const float* __restrict__ dbc, const float* __restrict__ A_log,
                        const float* __restrict__ cc, const float* __restrict__ Dp,
                        const float* __restrict__ xz,
                        __nv_bfloat16* __restrict__ yzh, __nv_bfloat16* __restrict__ yzl) {
    int i = blockIdx.x * blockDim.x + threadIdx.x;
    if (i >= NCHUNK * ED) return;
    int c = i / ED, e = i % ED;
    float A[NST], h[NST];
#pragma unroll
    for (int n = 0; n < NST; n++) {
        A[n] = -__expf(A_log[e * NST + n]);
        h[n] = cc[(size_t)i * NST + n];
    }
    float Dv = Dp[e];
    int t0 = c * CHUNK;
    for (int t = t0; t < t0 + CHUNK; t++) {
        float d  = delta[(size_t)t * ED + e];
        float xv = xb[(size_t)t * ED + e];
        float dx = d * xv;
        const float* Bt = dbc + (size_t)t * DXP + DTR;
        const float* Ct = dbc + (size_t)t * DXP + DTR + NST;
        float y = 0.f;
#pragma unroll
        for (int n = 0; n < NST; n++) {
            float a = __expf(d * A[n]);
            h[n] = fmaf(a, h[n], dx * Bt[n]);
            y = fmaf(h[n], Ct[n], y);
        }
        float zv = xz[(size_t)t * (2 * ED) + ED + e];
        float sz = zv / (1.f + __expf(-zv));
        float v = (y + xv * Dv) * sz;
        __nv_bfloat16 hb = __float2bfloat16(v);
        yzh[(size_t)t * ED + e] = hb;
        yzl[(size_t)t * ED + e] = __float2bfloat16(v - __bfloat162float(hb));
    }
}

// ---------------- host orchestration ----------------
extern "C" void kernel_launch(void* const* d_in, const int* in_sizes, int n_in,
                              void* d_out, int out_size) {
    const int*   tokens  = (const int*)d_in[0];
    const float* emb     = (const float*)d_in[1];
    const float* norm_w  = (const float*)d_in[2];
    const float* in_proj = (const float*)d_in[3];
    const float* conv_w  = (const float*)d_in[4];
    const float* conv_b  = (const float*)d_in[5];
    const float* x_proj  = (const float*)d_in[6];
    const float* dt_w    = (const float*)d_in[7];
    const float* dt_b    = (const float*)d_in[8];
    const float* A_log   = (const float*)d_in[9];
    const float* Dp      = (const float*)d_in[10];
    const float* out_prj = (const float*)d_in[11];
    const float* norm_f  = (const float*)d_in[12];
    const float* lm_head = (const float*)d_in[13];
    float* logits = (float*)d_out;

    float *x, *xz, *xb, *dbc, *delta, *cp, *cs, *cc;
    __nv_bfloat16 *ah, *al, *dh, *dl, *wh, *wl;
    cudaGetSymbolAddress((void**)&x,     g_x);
    cudaGetSymbolAddress((void**)&xz,    g_xz);
    cudaGetSymbolAddress((void**)&xb,    g_xb);
    cudaGetSymbolAddress((void**)&dbc,   g_dbc);
    cudaGetSymbolAddress((void**)&delta, g_delta);
    cudaGetSymbolAddress((void**)&cp,    g_cp);
    cudaGetSymbolAddress((void**)&cs,    g_cs);
    cudaGetSymbolAddress((void**)&cc,    g_cc);
    cudaGetSymbolAddress((void**)&ah,    g_ah);
    cudaGetSymbolAddress((void**)&al,    g_al);
    cudaGetSymbolAddress((void**)&dh,    g_dh);
    cudaGetSymbolAddress((void**)&dl,    g_dl);
    cudaGetSymbolAddress((void**)&wh,    g_wh);
    cudaGetSymbolAddress((void**)&wl,    g_wl);

    const int SM4 = 2 * (2 * 4 * 32 * ROWB + 2 * 128 * ROWB);   // 81920
    const int SM2 = 2 * (2 * 2 * 32 * ROWB + 2 * 128 * ROWB);   // 61440
    const int SM1 = 2 * (2 * 1 * 32 * ROWB + 2 * 128 * ROWB);   // 51200
    const int SMBIG = 2 * 4 * 256 * ROWB;                        // 163840
    static bool attr_done = false;
    if (!attr_done) {
        cudaFuncSetAttribute(hgemm_k<2,0>, cudaFuncAttributeMaxDynamicSharedMemorySize, SM2);
        cudaFuncSetAttribute(hgemm_k<2,2>, cudaFuncAttributeMaxDynamicSharedMemorySize, SM2);
        cudaFuncSetAttribute(hgemm_k<1,0>, cudaFuncAttributeMaxDynamicSharedMemorySize, SM1);
        cudaFuncSetAttribute(hgemm_k<4,1>, cudaFuncAttributeMaxDynamicSharedMemorySize, SM4);
        cudaFuncSetAttribute(hgemm2_k,     cudaFuncAttributeMaxDynamicSharedMemorySize, SMBIG);
        attr_done = true;
    }

    embed_k<<<(L * D + 255) / 256, 256>>>(tokens, emb, x);

    for (int l = 0; l < NL; l++) {
        rmsnorm_split_k<<<L, 256>>>(x, norm_w + l * D, ah, al);

        // xz = xn @ in_proj^T
        int nwi = 2 * ED * D;
        split4_k<<<(nwi / 4 + 255) / 256, 256>>>(
            (const float4*)(in_proj + (size_t)l * nwi), (__nv_bfloat162*)wh, (__nv_bfloat162*)wl, nwi / 4);
        hgemm_k<2,0><<<dim3(L / 64, 2 * ED / 128), 256, SM2>>>(
            ah, al, wh, wl, xz, D, 2 * ED, 2 * ED, nullptr);

        // conv + silu (also emits bf16 hi/lo of xb into ah/al)
        conv_silu_split_k<<<(L * ED + 255) / 256, 256>>>(
            xz, conv_w + (size_t)l * ED * DCONV, conv_b + l * ED, xb, ah, al);

        // dbc = xb @ x_proj^T  (N=80 padded to 128)
        split_pad_k<<<(128 * ED + 255) / 256, 256>>>(
            x_proj + (size_t)l * DXP * ED, wh, wl, 128, ED, DXP, ED, ED);
        hgemm_k<1,0><<<dim3(L / 32, 1), 256, SM1>>>(
            ah, al, wh, wl, dbc, ED, DXP, DXP, nullptr);

        // delta = softplus(dbc[:, :48] @ dt_w^T + dt_b)   (K=48 padded to 64)
        split_pad_k<<<(L * 64 + 255) / 256, 256>>>(dbc, dh, dl, L, 64, L, DTR, DXP);
        split_pad_k<<<(ED * 64 + 255) / 256, 256>>>(
            dt_w + (size_t)l * ED * DTR, wh, wl, ED, 64, ED, DTR, DTR);
        hgemm_k<4,1><<<dim3(L / 128, ED / 128), 256, SM4>>>(
            dh, dl, wh, wl, delta, 64, ED, ED, dt_b + l * ED);

        // selective scan (writes gated output as bf16 hi/lo into ah/al)
        scan1_k<<<(NCHUNK * ED) / 256, 256>>>(delta, xb, dbc,
                                              A_log + (size_t)l * ED * NST, cp, cs);
        carry_k<<<(ED * NST) / 256, 256>>>(cp, cs, cc);
        scan2_k<<<(NCHUNK * ED) / 256, 256>>>(delta, xb, dbc,
                                              A_log + (size_t)l * ED * NST, cc,
                                              Dp + l * ED, xz, ah, al);

        // x += yz @ out_proj^T
        int nwo = D * ED;
        split4_k<<<(nwo / 4 + 255) / 256, 256>>>(
            (const float4*)(out_prj + (size_t)l * nwo), (__nv_bfloat162*)wh, (__nv_bfloat162*)wl, nwo / 4);
        hgemm_k<2,2><<<dim3(L / 64, D / 128), 256, SM2>>>(
            ah, al, wh, wl, x, ED, D, D, nullptr);
    }

    rmsnorm_split_k<<<L, 256>>>(x, norm_f, ah, al);

    // logits = xn @ lm_head^T  (256x256 big-tile kernel)
    int nwl = VOCAB * D;
    split4_k<<<(nwl / 4 + 255) / 256, 256>>>(
        (const float4*)lm_head, (__nv_bfloat162*)wh, (__nv_bfloat162*)wl, nwl / 4);
    hgemm2_k<<<dim3(L / 256, VOCAB / 256), 512, SMBIG>>>(
        ah, al, wh, wl, logits, D, VOCAB);
}